// round 17
// baseline (speedup 1.0000x reference)
#include <cuda_runtime.h>
#include <cstdint>

// CTC forward-backward split, LOG2 domain, pure f32, REGISTER-RESIDENT state.
// 128 CTAs: CTA b (b<64) = ALPHA for batch b (t=0..m-1); CTA 64+b = BETA
// (t=il-1..m), m=il/2. State lives in registers; neighbors via shfl; warp
// boundaries via a 2-float-per-warp double-buffered smem halo. 3-term
// logaddexp in max-eliminated form (2 ex2 + 1 lg2). One barrier per step.
// Beta publishes gamma to global + flag; alpha combines, last CTA reduces.

#define T_DIM 2000
#define V_DIM 256
#define S_DIM 400
#define L_DIM 801
#define NTHREADS 832        // 26 warps
#define NW 26
#define QD 6
#define NEGF (-1e30f)

__device__ float g_partial[64];
__device__ float g_gamma[64][804];
__device__ int   g_flag[64];     // zero-init; alpha resets after consume
__device__ int   g_ctr = 0;

__device__ __forceinline__ float ex2f(float x) {
    float y; asm("ex2.approx.f32 %0, %1;" : "=f"(y) : "f"(x)); return y;
}
__device__ __forceinline__ float lg2f(float x) {
    float y; asm("lg2.approx.f32 %0, %1;" : "=f"(y) : "f"(x)); return y;
}

// max-eliminated 3-term logaddexp2 (R8-validated select logic)
__device__ __forceinline__ float laexp3(float x, float y, float z) {
    float m3 = fmaxf(fmaxf(x, y), z);
    bool  xm = (x >= y) && (x >= z);
    bool  zm = (!xm) && (z > y);
    float u  = xm ? y : x;
    float v  = zm ? y : z;
    return m3 + lg2f(1.0f + ex2f(u - m3) + ex2f(v - m3));
}

__global__ __launch_bounds__(NTHREADS, 1)
void ctc_kernel(const float* __restrict__ logp,
                const int*   __restrict__ targets,
                const int*   __restrict__ ilen,
                const int*   __restrict__ tlen,
                float*       __restrict__ out,
                int B)
{
    __shared__ float halo[2][NW][2];   // warp-boundary exchange, per parity
    __shared__ float red[32];
    __shared__ float Msh;

    const int b     = blockIdx.x & 63;
    const bool isA  = blockIdx.x < 64;
    const int tid   = threadIdx.x;
    const int lane  = tid & 31;
    const int w     = tid >> 5;
    const float* lpb = logp + (size_t)b * T_DIM * V_DIM;
    const int il  = ilen[b];
    const int tl  = tlen[b];
    const int end = 2 * tl;
    const int m   = il >> 1;
    const float l2e = 1.4426950408889634f;
    const int s = tid;

    int  lbl = 1;
    bool skA = false, skB = false;
    if ((s & 1) && s < L_DIM) {
        const int* tgt = targets + b * S_DIM;
        lbl = tgt[s >> 1];
        if (s >= 3) skA = (lbl != tgt[(s - 2) >> 1]);
        if (s + 2 < L_DIM) skB = (tgt[(s + 2) >> 1] != lbl);
    }
    const bool valid = (s < L_DIM) && (s <= end);
    const float* gcol = lpb + lbl;

    // halo init: both parities NEG
    if (tid < 2 * NW * 2) ((float*)halo)[tid] = NEGF;

    if (isA) {
        // ================= ALPHA: t = 0 .. m-1 =================
        const int lim = m - 1;
        float a = NEGF;
        if (tid == 0) a = lpb[1] * l2e;
        if (tid == 1 && valid) a = lpb[lbl] * l2e;

        float q0 = gcol[(size_t)min(1, lim) * V_DIM];
        float q1 = gcol[(size_t)min(2, lim) * V_DIM];
        float q2 = gcol[(size_t)min(3, lim) * V_DIM];
        float q3 = gcol[(size_t)min(4, lim) * V_DIM];
        float q4 = gcol[(size_t)min(5, lim) * V_DIM];
        float q5 = gcol[(size_t)min(6, lim) * V_DIM];
        __syncthreads();                         // halo NEG-init visible
        if (lane >= 30) halo[0][w][lane - 30] = a;   // alpha_0 halo (parity 0)
        __syncthreads();

        for (int t = 1; t <= lim; ++t) {
            float prv = a;
            float a1 = __shfl_up_sync(0xffffffffu, prv, 1);
            float a2 = __shfl_up_sync(0xffffffffu, prv, 2);
            float h0 = NEGF, h1 = NEGF;
            if (w > 0 && lane < 2) {
                h0 = halo[(t + 1) & 1][w - 1][0];   // state 32w-2
                h1 = halo[(t + 1) & 1][w - 1][1];   // state 32w-1
            }
            if (lane == 0)      { a1 = h1; a2 = h0; }
            else if (lane == 1) { a2 = h1; }

            float z  = skA ? a2 : NEGF;
            float nv = fmaf(q0, l2e, laexp3(prv, a1, z));
            a = valid ? nv : NEGF;
            if (lane >= 30) halo[t & 1][w][lane - 30] = a;

            q0 = q1; q1 = q2; q2 = q3; q3 = q4; q4 = q5;
            { int rr = t + QD; rr = rr < lim ? rr : lim;
              q5 = gcol[(size_t)rr * V_DIM]; }
            __syncthreads();
        }

        // ---- wait for gamma, combine ----
        if (tid == 0) {
            volatile int* fl = &g_flag[b];
            while (*fl == 0) { }
            __threadfence();
        }
        __syncthreads();

        float x = (s < L_DIM) ? (a + g_gamma[b][s]) : NEGF;

        float wm = x;
        #pragma unroll
        for (int o = 16; o; o >>= 1)
            wm = fmaxf(wm, __shfl_xor_sync(0xffffffffu, wm, o));
        if (lane == 0) red[w] = wm;
        __syncthreads();
        if (tid == 0) {
            float M = NEGF;
            for (int i = 0; i < NW; ++i) M = fmaxf(M, red[i]);
            Msh = M;
        }
        __syncthreads();
        float e = ex2f(x - Msh);
        #pragma unroll
        for (int o = 16; o; o >>= 1)
            e += __shfl_xor_sync(0xffffffffu, e, o);
        if (lane == 0) red[w] = e;
        __syncthreads();

        if (tid == 0) {
            float tot = 0.0f;
            for (int i = 0; i < NW; ++i) tot += red[i];
            float ll2 = Msh + lg2f(tot);
            float loss = -0.6931471805599453f * ll2;
            if (!(loss < 1e29f)) loss = 0.0f;
            g_partial[b] = loss / (float)tl;
            g_flag[b] = 0;                       // reset for next replay
            __threadfence();
            int done = atomicAdd(&g_ctr, 1);
            if (done == B - 1) {
                float v = 0.0f;
                for (int i = 0; i < B; ++i) v += g_partial[i];
                out[0] = v / (float)B;
                g_ctr = 0;
            }
        }
    } else {
        // ================= BETA: t = il-1 .. m =================
        float a = NEGF;
        if (s == end || s == end - 1)
            a = gcol[(size_t)(il - 1) * V_DIM] * l2e;

        float q0 = gcol[(size_t)max(il - 2, m) * V_DIM];
        float q1 = gcol[(size_t)max(il - 3, m) * V_DIM];
        float q2 = gcol[(size_t)max(il - 4, m) * V_DIM];
        float q3 = gcol[(size_t)max(il - 5, m) * V_DIM];
        float q4 = gcol[(size_t)max(il - 6, m) * V_DIM];
        float q5 = gcol[(size_t)max(il - 7, m) * V_DIM];
        __syncthreads();                         // halo NEG-init visible
        if (lane < 2) halo[(il - 1) & 1][w][lane] = a;   // beta_{il-1} halo
        __syncthreads();

        for (int t = il - 2; t >= m; --t) {
            float prv = a;
            float a1 = __shfl_down_sync(0xffffffffu, prv, 1);
            float a2 = __shfl_down_sync(0xffffffffu, prv, 2);
            float h0 = NEGF, h1 = NEGF;
            if (w < NW - 1 && lane >= 30) {
                h0 = halo[(t + 1) & 1][w + 1][0];   // state 32w+32
                h1 = halo[(t + 1) & 1][w + 1][1];   // state 32w+33
            }
            if (lane == 31)      { a1 = h0; a2 = h1; }
            else if (lane == 30) { a2 = h0; }

            float z  = skB ? a2 : NEGF;
            float nv = fmaf(q0, l2e, laexp3(prv, a1, z));
            a = valid ? nv : NEGF;
            if (lane < 2) halo[t & 1][w][lane] = a;

            q0 = q1; q1 = q2; q2 = q3; q3 = q4; q4 = q5;
            { int rr = t - QD; rr = rr > m ? rr : m;
              q5 = gcol[(size_t)rr * V_DIM]; }
            __syncthreads();
        }

        // gamma[s] = laexp2(beta_m[s], beta_m[s+1], skB? beta_m[s+2])
        {
            float a1 = __shfl_down_sync(0xffffffffu, a, 1);
            float a2 = __shfl_down_sync(0xffffffffu, a, 2);
            float h0 = NEGF, h1 = NEGF;
            if (w < NW - 1 && lane >= 30) {
                h0 = halo[m & 1][w + 1][0];
                h1 = halo[m & 1][w + 1][1];
            }
            if (lane == 31)      { a1 = h0; a2 = h1; }
            else if (lane == 30) { a2 = h0; }

            float zz = skB ? a2 : NEGF;
            float mm = fmaxf(fmaxf(a, a1), zz);
            float g;
            if (mm <= NEGF) g = NEGF;
            else g = mm + lg2f(ex2f(a - mm) + ex2f(a1 - mm) + ex2f(zz - mm));
            if (s < L_DIM) g_gamma[b][s] = g;
        }
        __threadfence();
        __syncthreads();
        if (tid == 0) g_flag[b] = 1;
    }
}

extern "C" void kernel_launch(void* const* d_in, const int* in_sizes, int n_in,
                              void* d_out, int out_size)
{
    const float* logp    = (const float*)d_in[0];
    const int*   targets = (const int*)d_in[1];
    const int*   il      = (const int*)d_in[2];
    const int*   tl      = (const int*)d_in[3];
    const int B = in_sizes[2];

    ctc_kernel<<<2 * B, NTHREADS>>>(logp, targets, il, tl, (float*)d_out, B);
}